// round 10
// baseline (speedup 1.0000x reference)
#include <cuda_runtime.h>
#include <cuda_fp16.h>
#include <math.h>

#define Bn 4
#define Cn 128
#define Hn 192
#define Wn 192
#define HWn 36864           // 192*192
#define NHn 2
#define Dn 64
#define O3 384              // 3*C
#define NPLANES 3072        // 2 streams * B * O3
#define NCHUNK 64
#define KCH 576             // 36864 / 64

// ---------------- scratch (device globals; allocation-free kernel_launch) ----
__device__ __half g_qkv[(size_t)2 * Bn * O3 * HWn];       // fp16 conv+leaky, both streams
__device__ float g_sum[NPLANES];
__device__ float g_sumsq[NPLANES];
__device__ float g_scale[NPLANES];
__device__ float g_shift[NPLANES];
__device__ __half g_q[(size_t)Bn * NHn * Dn * HWn];
__device__ __half g_k[(size_t)Bn * NHn * Dn * HWn];
__device__ __half g_v[(size_t)Bn * NHn * Dn * HWn];
__device__ __half g_ao[(size_t)Bn * NHn * Dn * HWn];
__device__ float g_sqq[Bn * NHn * Dn];
__device__ float g_sqk[Bn * NHn * Dn];
__device__ float g_attn_part[(size_t)NCHUNK * Bn * NHn * Dn * Dn];
__device__ float g_attn[Bn * NHn * Dn * Dn];

// ---------------- stage A: depthwise conv3x3 + leaky + stats (fp16 out) -----
// One smem-tile read feeds all 3 e-outputs.
__global__ void __launch_bounds__(256)
kA(const float* __restrict__ x, const float* __restrict__ ir,
   const float* __restrict__ w, const float* __restrict__ bias) {
    int rt = blockIdx.x;            // 0..11 row tiles of 16
    int c  = blockIdx.y;            // 0..127
    int zb = blockIdx.z;            // 0..7 : stream*4 + b
    int stream = zb >> 2, b = zb & 3;
    const float* in = (stream ? ir : x) + (size_t)(b * Cn + c) * HWn;

    __shared__ float s_in[18][194];
    __shared__ float s_sum[3], s_sq[3];
    int r0 = rt * 16;
    for (int idx = threadIdx.x; idx < 18 * 194; idx += 256) {
        int rr = idx / 194, cc = idx % 194;
        int gr = r0 + rr - 1, gc = cc - 1;
        float v = 0.f;
        if (gr >= 0 && gr < Hn && gc >= 0 && gc < Wn) v = in[gr * Wn + gc];
        s_in[rr][cc] = v;
    }
    if (threadIdx.x < 3) { s_sum[threadIdx.x] = 0.f; s_sq[threadIdx.x] = 0.f; }
    __syncthreads();

    float wreg[27], bb3[3];
    #pragma unroll
    for (int e = 0; e < 3; e++) {
        const float* wp = w + (size_t)(3 * c + e) * 9;
        #pragma unroll
        for (int j = 0; j < 9; j++) wreg[e * 9 + j] = wp[j];
        bb3[e] = bias[3 * c + e];
    }
    float ls[3] = {0.f, 0.f, 0.f}, ls2[3] = {0.f, 0.f, 0.f};
    __half* outp0 = g_qkv + ((size_t)zb * O3 + 3 * c) * HWn;

    for (int p4 = threadIdx.x; p4 < 768; p4 += 256) {
        int lr = p4 / 48, lc = (p4 % 48) * 4;
        float a0[6], a1[6], a2[6];
        #pragma unroll
        for (int j = 0; j < 6; j++) {
            a0[j] = s_in[lr][lc + j];
            a1[j] = s_in[lr + 1][lc + j];
            a2[j] = s_in[lr + 2][lc + j];
        }
        size_t pofs = (size_t)(r0 + lr) * Wn + lc;
        #pragma unroll
        for (int e = 0; e < 3; e++) {
            const float* wp = &wreg[e * 9];
            float o4[4];
            #pragma unroll
            for (int j = 0; j < 4; j++) {
                float acc = bb3[e]
                    + wp[0] * a0[j] + wp[1] * a0[j + 1] + wp[2] * a0[j + 2]
                    + wp[3] * a1[j] + wp[4] * a1[j + 1] + wp[5] * a1[j + 2]
                    + wp[6] * a2[j] + wp[7] * a2[j + 1] + wp[8] * a2[j + 2];
                acc = (acc >= 0.f) ? acc : 0.05f * acc;
                o4[j] = acc;
                ls[e] += acc; ls2[e] += acc * acc;
            }
            __half2 h01 = __floats2half2_rn(o4[0], o4[1]);
            __half2 h23 = __floats2half2_rn(o4[2], o4[3]);
            uint2 pack;
            pack.x = *reinterpret_cast<unsigned*>(&h01);
            pack.y = *reinterpret_cast<unsigned*>(&h23);
            *reinterpret_cast<uint2*>(outp0 + (size_t)e * HWn + pofs) = pack;
        }
    }
    #pragma unroll
    for (int e = 0; e < 3; e++) {
        float a = ls[e], a2 = ls2[e];
        #pragma unroll
        for (int off = 16; off; off >>= 1) {
            a  += __shfl_down_sync(0xffffffffu, a, off);
            a2 += __shfl_down_sync(0xffffffffu, a2, off);
        }
        if ((threadIdx.x & 31) == 0) {
            atomicAdd(&s_sum[e], a);
            atomicAdd(&s_sq[e], a2);
        }
    }
    __syncthreads();
    if (threadIdx.x < 3) {
        int o = 3 * c + threadIdx.x;
        atomicAdd(&g_sum[zb * O3 + o], s_sum[threadIdx.x]);
        atomicAdd(&g_sumsq[zb * O3 + o], s_sq[threadIdx.x]);
    }
}

__global__ void kFin(const float* __restrict__ gamma, const float* __restrict__ beta) {
    int i = blockIdx.x * 256 + threadIdx.x;
    if (i >= NPLANES) return;
    const float invN = 1.f / (float)HWn;
    float mean = g_sum[i] * invN;
    float var  = g_sumsq[i] * invN - mean * mean;
    float istd = rsqrtf(var + 1e-5f);
    int o = i % O3;
    float sc = gamma[o] * istd;
    g_scale[i] = sc;
    g_shift[i] = beta[o] - mean * sc;
}

// ------------- stage B: 4->2 conv over (D=64, HW) plane, normalized input ----
// One fused kernel for q/k/v: blockIdx.z = b*3 + e; fp16 outputs + q/k sumsq.
__global__ void __launch_bounds__(256, 4)
kB(const float* __restrict__ wq, const float* __restrict__ bq,
   const float* __restrict__ wk, const float* __restrict__ bk,
   const float* __restrict__ wv, const float* __restrict__ bv,
   __half* __restrict__ outq, __half* __restrict__ outk, __half* __restrict__ outv) {
    int nt = blockIdx.x;   // 144 tiles of 256 cols
    int dt = blockIdx.y;   // 8 tiles of 8 rows
    int zz = blockIdx.z;   // 12 : b*3 + e
    int b = zz / 3, e = zz % 3;
    int n0 = nt * 256, d0 = dt * 8;

    const float* wconv = (e == 0) ? wq : (e == 1) ? wk : wv;
    const float* bias  = (e == 0) ? bq : (e == 1) ? bk : bv;
    __half* out        = (e == 0) ? outq : (e == 1) ? outk : outv;

    __shared__ float s_in[4][10][258];
    __shared__ float s_w[72];
    __shared__ float s_b[2];
    __shared__ float s_sqred[16];
    if (threadIdx.x < 72) s_w[threadIdx.x] = wconv[threadIdx.x];
    if (threadIdx.x < 2)  s_b[threadIdx.x] = bias[threadIdx.x];
    if (threadIdx.x < 16) s_sqred[threadIdx.x] = 0.f;

    int warp = threadIdx.x >> 5, lane = threadIdx.x & 31;
    for (int row = warp; row < 40; row += 8) {
        int ci = row / 10, rr = row % 10;
        int d = d0 + rr - 1;
        bool valid = (d >= 0 && d < Dn);
        float* dst = &s_in[ci][rr][0];
        if (valid) {
            int stream = ci >> 1, head = ci & 1;
            int plane = (stream * 4 + b) * O3 + 3 * (head * Dn + d) + e;
            float sc = g_scale[plane];
            float sh = g_shift[plane];
            const __half* srcH = g_qkv + (size_t)plane * HWn;
            #pragma unroll
            for (int j = lane; j < 128; j += 32) {
                __half2 h = *reinterpret_cast<const __half2*>(srcH + n0 + 2 * j);
                float2 f = __half22float2(h);
                dst[1 + 2 * j] = fmaf(f.x, sc, sh);
                dst[2 + 2 * j] = fmaf(f.y, sc, sh);
            }
            if (lane == 0) {
                dst[0]   = (n0 > 0) ? fmaf(__half2float(srcH[n0 - 1]), sc, sh) : 0.f;
                dst[257] = (n0 + 256 < HWn) ? fmaf(__half2float(srcH[n0 + 256]), sc, sh) : 0.f;
            }
        } else {
            #pragma unroll
            for (int cc = lane; cc < 258; cc += 32) dst[cc] = 0.f;
        }
    }
    __syncthreads();

    int ln = threadIdx.x;
    #pragma unroll
    for (int ho = 0; ho < 2; ho++) {
        const float* wp = &s_w[ho * 36];
        float bb = s_b[ho];
        #pragma unroll
        for (int ld = 0; ld < 8; ld++) {
            float acc = bb;
            #pragma unroll
            for (int ci = 0; ci < 4; ci++) {
                #pragma unroll
                for (int dd = 0; dd < 3; dd++) {
                    acc += wp[ci * 9 + dd * 3 + 0] * s_in[ci][ld + dd][ln]
                         + wp[ci * 9 + dd * 3 + 1] * s_in[ci][ld + dd][ln + 1]
                         + wp[ci * 9 + dd * 3 + 2] * s_in[ci][ld + dd][ln + 2];
                }
            }
            acc = (acc >= 0.f) ? acc : 0.05f * acc;
            out[((size_t)(b * NHn + ho) * Dn + d0 + ld) * HWn + n0 + ln] = __float2half_rn(acc);
            if (e < 2) {
                float sq = acc * acc;
                #pragma unroll
                for (int off = 16; off; off >>= 1)
                    sq += __shfl_down_sync(0xffffffffu, sq, off);
                if (lane == 0) atomicAdd(&s_sqred[ho * 8 + ld], sq);
            }
        }
    }
    if (e < 2) {
        __syncthreads();
        if (threadIdx.x < 16) {
            int ho = threadIdx.x >> 3, ld = threadIdx.x & 7;
            float* gdst = (e == 0) ? g_sqq : g_sqk;
            atomicAdd(&gdst[(b * NHn + ho) * Dn + d0 + ld], s_sqred[threadIdx.x]);
        }
    }
}

// ---------------- GEMM1: attn_part = q_slice @ k_slice^T (fp16 in) ----------
__global__ void kGemm1() {
    int ch = blockIdx.x;    // 0..63
    int bh = blockIdx.y;    // 0..7
    int k0 = ch * KCH;
    __shared__ float s_q[64][33];
    __shared__ float s_k[64][33];
    float acc[4][4];
    #pragma unroll
    for (int i = 0; i < 4; i++)
        #pragma unroll
        for (int l = 0; l < 4; l++) acc[i][l] = 0.f;

    int tx = threadIdx.x & 15, ty = threadIdx.x >> 4;
    const __half* qp = g_q + (size_t)bh * Dn * HWn;
    const __half* kp = g_k + (size_t)bh * Dn * HWn;

    for (int kk = 0; kk < KCH; kk += 32) {
        // per operand: 64 rows x 16 half2 = 1024 half2; each thread 4
        #pragma unroll
        for (int it = 0; it < 4; it++) {
            int idx = threadIdx.x + it * 256;
            int r = idx >> 4, h2 = idx & 15;
            __half2 vq = *(const __half2*)(qp + (size_t)r * HWn + k0 + kk + h2 * 2);
            __half2 vk = *(const __half2*)(kp + (size_t)r * HWn + k0 + kk + h2 * 2);
            float2 fq = __half22float2(vq);
            float2 fk = __half22float2(vk);
            s_q[r][h2 * 2 + 0] = fq.x; s_q[r][h2 * 2 + 1] = fq.y;
            s_k[r][h2 * 2 + 0] = fk.x; s_k[r][h2 * 2 + 1] = fk.y;
        }
        __syncthreads();
        #pragma unroll
        for (int j = 0; j < 32; j++) {
            float a[4], bb[4];
            #pragma unroll
            for (int i = 0; i < 4; i++) a[i]  = s_q[ty * 4 + i][j];
            #pragma unroll
            for (int i = 0; i < 4; i++) bb[i] = s_k[tx * 4 + i][j];
            #pragma unroll
            for (int i = 0; i < 4; i++)
                #pragma unroll
                for (int l = 0; l < 4; l++) acc[i][l] += a[i] * bb[l];
        }
        __syncthreads();
    }
    float* outp = g_attn_part + ((size_t)ch * 8 + bh) * 4096;
    #pragma unroll
    for (int i = 0; i < 4; i++)
        #pragma unroll
        for (int l = 0; l < 4; l++)
            outp[(ty * 4 + i) * 64 + tx * 4 + l] = acc[i][l];
}

// ---------------- reduce partials + normalize + softmax ---------------------
__global__ void __launch_bounds__(1024) kSoftmax(const float* __restrict__ t) {
    int bh = blockIdx.x;            // 0..7
    int h = bh & 1;
    __shared__ float s_attn[4096];
    __shared__ float s_rq[64], s_rk[64];
    if (threadIdx.x < 64) {
        s_rq[threadIdx.x] = 1.f / fmaxf(sqrtf(g_sqq[bh * 64 + threadIdx.x]), 1e-12f);
        s_rk[threadIdx.x] = 1.f / fmaxf(sqrtf(g_sqk[bh * 64 + threadIdx.x]), 1e-12f);
    }
    {
        float s0 = 0.f, s1 = 0.f, s2 = 0.f, s3 = 0.f;
        const float* base = g_attn_part + (size_t)bh * 4096 + threadIdx.x;
        for (int ch = 0; ch < NCHUNK; ch++) {
            const float* p = base + (size_t)ch * 8 * 4096;
            s0 += p[0];
            s1 += p[1024];
            s2 += p[2048];
            s3 += p[3072];
        }
        s_attn[threadIdx.x]        = s0;
        s_attn[threadIdx.x + 1024] = s1;
        s_attn[threadIdx.x + 2048] = s2;
        s_attn[threadIdx.x + 3072] = s3;
    }
    __syncthreads();
    if (threadIdx.x < 64) {
        int d = threadIdx.x;
        float tv = t[h];
        float row[64];
        float m = -1e30f;
        #pragma unroll
        for (int e2 = 0; e2 < 64; e2++) {
            float v = s_attn[d * 64 + e2] * s_rq[d] * s_rk[e2] * tv;
            row[e2] = v;
            m = fmaxf(m, v);
        }
        float ssum = 0.f;
        #pragma unroll
        for (int e2 = 0; e2 < 64; e2++) {
            row[e2] = expf(row[e2] - m);
            ssum += row[e2];
        }
        float inv = 1.f / ssum;
        #pragma unroll
        for (int e2 = 0; e2 < 64; e2++)
            g_attn[bh * 4096 + d * 64 + e2] = row[e2] * inv;
    }
}

// ---------------- GEMM2: out = attn @ v (fp16 v, fp16 out) ------------------
__global__ void __launch_bounds__(256, 2) kGemm2() {
    int nt = blockIdx.x;   // 144
    int bh = blockIdx.y;   // 8
    int n0 = nt * 256;
    __shared__ float4 s_a[1024];   // attn[d][e], e packed in float4
    float* s_af = (float*)s_a;
    for (int idx = threadIdx.x; idx < 4096; idx += 256)
        s_af[idx] = g_attn[bh * 4096 + idx];
    __syncthreads();

    float acc[64];
    #pragma unroll
    for (int d = 0; d < 64; d++) acc[d] = 0.f;

    const __half* vp = g_v + (size_t)bh * Dn * HWn + n0 + threadIdx.x;
    for (int e4 = 0; e4 < 16; e4++) {
        float v0 = __half2float(vp[(size_t)(e4 * 4 + 0) * HWn]);
        float v1 = __half2float(vp[(size_t)(e4 * 4 + 1) * HWn]);
        float v2 = __half2float(vp[(size_t)(e4 * 4 + 2) * HWn]);
        float v3 = __half2float(vp[(size_t)(e4 * 4 + 3) * HWn]);
        #pragma unroll
        for (int d = 0; d < 64; d++) {
            float4 a = s_a[d * 16 + e4];
            acc[d] += a.x * v0 + a.y * v1 + a.z * v2 + a.w * v3;
        }
    }
    __half* op = g_ao + (size_t)bh * Dn * HWn + n0 + threadIdx.x;
    #pragma unroll
    for (int d = 0; d < 64; d++) op[(size_t)d * HWn] = __float2half_rn(acc[d]);
}

// ---------------- stage D: rearrange + depthwise fuse conv + leaky ----------
__global__ void kD(const float* __restrict__ w, const float* __restrict__ bias,
                   float* __restrict__ out) {
    int rt = blockIdx.x;  // 12
    int c  = blockIdx.y;  // 128
    int b  = blockIdx.z;  // 4
    int d = c >> 1, h = c & 1;
    const __half* in = g_ao + ((size_t)(b * NHn + h) * Dn + d) * HWn;

    __shared__ float s_in[18][194];
    int r0 = rt * 16;
    for (int idx = threadIdx.x; idx < 18 * 194; idx += 256) {
        int rr = idx / 194, cc = idx % 194;
        int gr = r0 + rr - 1, gc = cc - 1;
        float v = 0.f;
        if (gr >= 0 && gr < Hn && gc >= 0 && gc < Wn) v = __half2float(in[gr * Wn + gc]);
        s_in[rr][cc] = v;
    }
    __syncthreads();

    const float* wp = w + c * 9;
    float w0 = wp[0], w1 = wp[1], w2 = wp[2], w3 = wp[3], w4 = wp[4],
          w5 = wp[5], w6 = wp[6], w7 = wp[7], w8 = wp[8];
    float bb = bias[c];
    float* outp = out + (size_t)(b * Cn + c) * HWn;
    for (int pix = threadIdx.x; pix < 16 * Wn; pix += 256) {
        int lr = pix / Wn, lc = pix % Wn;
        float acc = bb
            + w0 * s_in[lr][lc]     + w1 * s_in[lr][lc + 1]     + w2 * s_in[lr][lc + 2]
            + w3 * s_in[lr + 1][lc] + w4 * s_in[lr + 1][lc + 1] + w5 * s_in[lr + 1][lc + 2]
            + w6 * s_in[lr + 2][lc] + w7 * s_in[lr + 2][lc + 1] + w8 * s_in[lr + 2][lc + 2];
        acc = (acc >= 0.f) ? acc : 0.05f * acc;
        outp[(r0 + lr) * Wn + lc] = acc;
    }
}

// ---------------- launch ----------------------------------------------------
extern "C" void kernel_launch(void* const* d_in, const int* in_sizes, int n_in,
                              void* d_out, int out_size) {
    const float* x     = (const float*)d_in[0];
    const float* ir    = (const float*)d_in[1];
    const float* w_qkv = (const float*)d_in[2];
    const float* b_qkv = (const float*)d_in[3];
    const float* gamma = (const float*)d_in[4];
    const float* beta  = (const float*)d_in[5];
    const float* wq    = (const float*)d_in[6];
    const float* bq    = (const float*)d_in[7];
    const float* wk    = (const float*)d_in[8];
    const float* bk    = (const float*)d_in[9];
    const float* wv    = (const float*)d_in[10];
    const float* bv    = (const float*)d_in[11];
    const float* t     = (const float*)d_in[12];
    const float* w_fus = (const float*)d_in[13];
    const float* b_fus = (const float*)d_in[14];
    float* out = (float*)d_out;

    void *pSum, *pSq, *pQ, *pK, *pV, *pSqq, *pSqk;
    cudaGetSymbolAddress(&pSum, g_sum);
    cudaGetSymbolAddress(&pSq, g_sumsq);
    cudaGetSymbolAddress(&pQ, g_q);
    cudaGetSymbolAddress(&pK, g_k);
    cudaGetSymbolAddress(&pV, g_v);
    cudaGetSymbolAddress(&pSqq, g_sqq);
    cudaGetSymbolAddress(&pSqk, g_sqk);

    cudaMemsetAsync(pSum, 0, NPLANES * sizeof(float));
    cudaMemsetAsync(pSq, 0, NPLANES * sizeof(float));
    cudaMemsetAsync(pSqq, 0, Bn * NHn * Dn * sizeof(float));
    cudaMemsetAsync(pSqk, 0, Bn * NHn * Dn * sizeof(float));

    kA<<<dim3(12, 128, 8), 256>>>(x, ir, w_qkv, b_qkv);
    kFin<<<(NPLANES + 255) / 256, 256>>>(gamma, beta);

    kB<<<dim3(144, 8, 12), 256>>>(wq, bq, wk, bk, wv, bv,
                                  (__half*)pQ, (__half*)pK, (__half*)pV);

    kGemm1<<<dim3(NCHUNK, 8), 256>>>();
    kSoftmax<<<8, 1024>>>(t);
    kGemm2<<<dim3(144, 8), 256>>>();

    kD<<<dim3(12, 128, 4), 256>>>(w_fus, b_fus, out);
}

// round 12
// speedup vs baseline: 1.3285x; 1.3285x over previous
#include <cuda_runtime.h>
#include <cuda_fp16.h>
#include <math.h>

#define Bn 4
#define Cn 128
#define Hn 192
#define Wn 192
#define HWn 36864           // 192*192
#define NHn 2
#define Dn 64
#define O3 384              // 3*C
#define NPLANES 3072        // 2 streams * B * O3
#define NCHUNK 32
#define KCH 1152            // 36864 / 32

// ---------------- scratch (device globals; allocation-free kernel_launch) ----
__device__ __half g_qkv[(size_t)2 * Bn * O3 * HWn];       // fp16 conv+leaky, both streams
__device__ float g_sum[NPLANES];
__device__ float g_sumsq[NPLANES];
__device__ float g_scale[NPLANES];
__device__ float g_shift[NPLANES];
__device__ float g_q[(size_t)Bn * NHn * Dn * HWn];
__device__ float g_k[(size_t)Bn * NHn * Dn * HWn];
__device__ float g_v[(size_t)Bn * NHn * Dn * HWn];
__device__ float g_ao[(size_t)Bn * NHn * Dn * HWn];
__device__ float g_sqq[Bn * NHn * Dn];
__device__ float g_sqk[Bn * NHn * Dn];
__device__ float g_attn_part[(size_t)NCHUNK * Bn * NHn * Dn * Dn];
__device__ float g_attn[Bn * NHn * Dn * Dn];

// ---------------- stage A: depthwise conv3x3 + leaky + stats (fp16 out) -----
__global__ void __launch_bounds__(256)
kA(const float* __restrict__ x, const float* __restrict__ ir,
   const float* __restrict__ w, const float* __restrict__ bias) {
    int rt = blockIdx.x;            // 0..11 row tiles of 16
    int c  = blockIdx.y;            // 0..127
    int zb = blockIdx.z;            // 0..7 : stream*4 + b
    int stream = zb >> 2, b = zb & 3;
    const float* in = (stream ? ir : x) + (size_t)(b * Cn + c) * HWn;

    __shared__ float s_in[18][194];
    __shared__ float s_sum[3], s_sq[3];
    int r0 = rt * 16;
    for (int idx = threadIdx.x; idx < 18 * 194; idx += 256) {
        int rr = idx / 194, cc = idx % 194;
        int gr = r0 + rr - 1, gc = cc - 1;
        float v = 0.f;
        if (gr >= 0 && gr < Hn && gc >= 0 && gc < Wn) v = in[gr * Wn + gc];
        s_in[rr][cc] = v;
    }
    if (threadIdx.x < 3) { s_sum[threadIdx.x] = 0.f; s_sq[threadIdx.x] = 0.f; }
    __syncthreads();

    #pragma unroll
    for (int e = 0; e < 3; e++) {
        int o = 3 * c + e;
        const float* wp = w + o * 9;
        float w0 = wp[0], w1 = wp[1], w2 = wp[2], w3 = wp[3], w4 = wp[4],
              w5 = wp[5], w6 = wp[6], w7 = wp[7], w8 = wp[8];
        float bb = bias[o];
        float ls = 0.f, ls2 = 0.f;
        __half* outp = g_qkv + ((size_t)zb * O3 + o) * HWn;
        for (int p4 = threadIdx.x; p4 < 768; p4 += 256) {
            int lr = p4 / 48, lc = (p4 % 48) * 4;
            float a0[6], a1[6], a2[6];
            #pragma unroll
            for (int j = 0; j < 6; j++) {
                a0[j] = s_in[lr][lc + j];
                a1[j] = s_in[lr + 1][lc + j];
                a2[j] = s_in[lr + 2][lc + j];
            }
            float o4[4];
            #pragma unroll
            for (int j = 0; j < 4; j++) {
                float acc = bb
                    + w0 * a0[j] + w1 * a0[j + 1] + w2 * a0[j + 2]
                    + w3 * a1[j] + w4 * a1[j + 1] + w5 * a1[j + 2]
                    + w6 * a2[j] + w7 * a2[j + 1] + w8 * a2[j + 2];
                acc = (acc >= 0.f) ? acc : 0.05f * acc;
                o4[j] = acc;
                ls += acc; ls2 += acc * acc;
            }
            __half2 h01 = __floats2half2_rn(o4[0], o4[1]);
            __half2 h23 = __floats2half2_rn(o4[2], o4[3]);
            uint2 pack;
            pack.x = *reinterpret_cast<unsigned*>(&h01);
            pack.y = *reinterpret_cast<unsigned*>(&h23);
            *reinterpret_cast<uint2*>(outp + (size_t)(r0 + lr) * Wn + lc) = pack;
        }
        #pragma unroll
        for (int off = 16; off; off >>= 1) {
            ls  += __shfl_down_sync(0xffffffffu, ls, off);
            ls2 += __shfl_down_sync(0xffffffffu, ls2, off);
        }
        if ((threadIdx.x & 31) == 0) {
            atomicAdd(&s_sum[e], ls);
            atomicAdd(&s_sq[e], ls2);
        }
    }
    __syncthreads();
    if (threadIdx.x < 3) {
        int o = 3 * c + threadIdx.x;
        atomicAdd(&g_sum[zb * O3 + o], s_sum[threadIdx.x]);
        atomicAdd(&g_sumsq[zb * O3 + o], s_sq[threadIdx.x]);
    }
}

__global__ void kFin(const float* __restrict__ gamma, const float* __restrict__ beta) {
    int i = blockIdx.x * 256 + threadIdx.x;
    if (i >= NPLANES) return;
    const float invN = 1.f / (float)HWn;
    float mean = g_sum[i] * invN;
    float var  = g_sumsq[i] * invN - mean * mean;
    float istd = rsqrtf(var + 1e-5f);
    int o = i % O3;
    float sc = gamma[o] * istd;
    g_scale[i] = sc;
    g_shift[i] = beta[o] - mean * sc;
}

// ------------- stage B: 4->2 conv over (D=64, HW) plane, normalized input ----
// One fused kernel for q/k/v: blockIdx.z = b*3 + e. Register-cached columns.
__global__ void __launch_bounds__(256, 4)
kB(const float* __restrict__ wq, const float* __restrict__ bq,
   const float* __restrict__ wk, const float* __restrict__ bk,
   const float* __restrict__ wv, const float* __restrict__ bv,
   float* __restrict__ outq, float* __restrict__ outk, float* __restrict__ outv) {
    int nt = blockIdx.x;   // 144 tiles of 256 cols
    int dt = blockIdx.y;   // 8 tiles of 8 rows
    int zz = blockIdx.z;   // 12 : b*3 + e
    int b = zz / 3, e = zz % 3;
    int n0 = nt * 256, d0 = dt * 8;

    const float* wconv = (e == 0) ? wq : (e == 1) ? wk : wv;
    const float* bias  = (e == 0) ? bq : (e == 1) ? bk : bv;
    float* out         = (e == 0) ? outq : (e == 1) ? outk : outv;

    __shared__ float s_in[4][10][258];
    __shared__ float s_w[72];
    __shared__ float s_b[2];
    __shared__ float s_sqred[16];
    if (threadIdx.x < 72) s_w[threadIdx.x] = wconv[threadIdx.x];
    if (threadIdx.x < 2)  s_b[threadIdx.x] = bias[threadIdx.x];
    if (threadIdx.x < 16) s_sqred[threadIdx.x] = 0.f;

    int warp = threadIdx.x >> 5, lane = threadIdx.x & 31;
    for (int row = warp; row < 40; row += 8) {
        int ci = row / 10, rr = row % 10;
        int d = d0 + rr - 1;
        bool valid = (d >= 0 && d < Dn);
        float* dst = &s_in[ci][rr][0];
        if (valid) {
            int stream = ci >> 1, head = ci & 1;
            int plane = (stream * 4 + b) * O3 + 3 * (head * Dn + d) + e;
            float sc = g_scale[plane];
            float sh = g_shift[plane];
            const __half* srcH = g_qkv + (size_t)plane * HWn;
            #pragma unroll
            for (int j = lane; j < 128; j += 32) {
                __half2 h = *reinterpret_cast<const __half2*>(srcH + n0 + 2 * j);
                float2 f = __half22float2(h);
                dst[1 + 2 * j] = fmaf(f.x, sc, sh);
                dst[2 + 2 * j] = fmaf(f.y, sc, sh);
            }
            if (lane == 0) {
                dst[0]   = (n0 > 0) ? fmaf(__half2float(srcH[n0 - 1]), sc, sh) : 0.f;
                dst[257] = (n0 + 256 < HWn) ? fmaf(__half2float(srcH[n0 + 256]), sc, sh) : 0.f;
            }
        } else {
            #pragma unroll
            for (int cc = lane; cc < 258; cc += 32) dst[cc] = 0.f;
        }
    }
    __syncthreads();

    int ln = threadIdx.x;
    float acc[16];
    #pragma unroll
    for (int i = 0; i < 16; i++) acc[i] = (i < 8) ? s_b[0] : s_b[1];

    #pragma unroll
    for (int ci = 0; ci < 4; ci++) {
        // register-cache the 3 columns for all 10 rows
        float c0[10], c1[10], c2[10];
        #pragma unroll
        for (int r = 0; r < 10; r++) {
            c0[r] = s_in[ci][r][ln];
            c1[r] = s_in[ci][r][ln + 1];
            c2[r] = s_in[ci][r][ln + 2];
        }
        #pragma unroll
        for (int ho = 0; ho < 2; ho++) {
            const float* wp = &s_w[ho * 36 + ci * 9];
            float w0 = wp[0], w1 = wp[1], w2 = wp[2], w3 = wp[3], w4 = wp[4],
                  w5 = wp[5], w6 = wp[6], w7 = wp[7], w8 = wp[8];
            #pragma unroll
            for (int ld = 0; ld < 8; ld++) {
                acc[ho * 8 + ld] +=
                      w0 * c0[ld]     + w1 * c1[ld]     + w2 * c2[ld]
                    + w3 * c0[ld + 1] + w4 * c1[ld + 1] + w5 * c2[ld + 1]
                    + w6 * c0[ld + 2] + w7 * c1[ld + 2] + w8 * c2[ld + 2];
            }
        }
    }

    #pragma unroll
    for (int ho = 0; ho < 2; ho++) {
        #pragma unroll
        for (int ld = 0; ld < 8; ld++) {
            float a = acc[ho * 8 + ld];
            a = (a >= 0.f) ? a : 0.05f * a;
            out[((size_t)(b * NHn + ho) * Dn + d0 + ld) * HWn + n0 + ln] = a;
            if (e < 2) {
                float sq = a * a;
                #pragma unroll
                for (int off = 16; off; off >>= 1)
                    sq += __shfl_down_sync(0xffffffffu, sq, off);
                if (lane == 0) atomicAdd(&s_sqred[ho * 8 + ld], sq);
            }
        }
    }
    if (e < 2) {
        __syncthreads();
        if (threadIdx.x < 16) {
            int ho = threadIdx.x >> 3, ld = threadIdx.x & 7;
            float* gdst = (e == 0) ? g_sqq : g_sqk;
            atomicAdd(&gdst[(b * NHn + ho) * Dn + d0 + ld], s_sqred[threadIdx.x]);
        }
    }
}

// ---------------- GEMM1: attn_part = q_slice @ k_slice^T --------------------
// Transposed smem (K-major) so inner loop uses LDS.128.
__global__ void kGemm1() {
    int ch = blockIdx.x;    // 0..31
    int bh = blockIdx.y;    // 0..7
    int k0 = ch * KCH;
    __shared__ float s_qT[32][68];   // [k][row], row-stride 68 floats = 16B-aligned
    __shared__ float s_kT[32][68];
    float acc[4][4];
    #pragma unroll
    for (int i = 0; i < 4; i++)
        #pragma unroll
        for (int l = 0; l < 4; l++) acc[i][l] = 0.f;

    int tx = threadIdx.x & 15, ty = threadIdx.x >> 4;
    const float* qp = g_q + (size_t)bh * Dn * HWn;
    const float* kp = g_k + (size_t)bh * Dn * HWn;

    for (int kk = 0; kk < KCH; kk += 32) {
        #pragma unroll
        for (int it = 0; it < 2; it++) {
            int idx = threadIdx.x + it * 256;
            int r = idx >> 3, c4 = idx & 7;
            float4 vq = *(const float4*)(qp + (size_t)r * HWn + k0 + kk + c4 * 4);
            float4 vk = *(const float4*)(kp + (size_t)r * HWn + k0 + kk + c4 * 4);
            s_qT[c4 * 4 + 0][r] = vq.x; s_qT[c4 * 4 + 1][r] = vq.y;
            s_qT[c4 * 4 + 2][r] = vq.z; s_qT[c4 * 4 + 3][r] = vq.w;
            s_kT[c4 * 4 + 0][r] = vk.x; s_kT[c4 * 4 + 1][r] = vk.y;
            s_kT[c4 * 4 + 2][r] = vk.z; s_kT[c4 * 4 + 3][r] = vk.w;
        }
        __syncthreads();
        #pragma unroll
        for (int j = 0; j < 32; j++) {
            float4 a  = *(const float4*)&s_qT[j][ty * 4];
            float4 bb = *(const float4*)&s_kT[j][tx * 4];
            acc[0][0] += a.x * bb.x; acc[0][1] += a.x * bb.y;
            acc[0][2] += a.x * bb.z; acc[0][3] += a.x * bb.w;
            acc[1][0] += a.y * bb.x; acc[1][1] += a.y * bb.y;
            acc[1][2] += a.y * bb.z; acc[1][3] += a.y * bb.w;
            acc[2][0] += a.z * bb.x; acc[2][1] += a.z * bb.y;
            acc[2][2] += a.z * bb.z; acc[2][3] += a.z * bb.w;
            acc[3][0] += a.w * bb.x; acc[3][1] += a.w * bb.y;
            acc[3][2] += a.w * bb.z; acc[3][3] += a.w * bb.w;
        }
        __syncthreads();
    }
    float* outp = g_attn_part + ((size_t)ch * 8 + bh) * 4096;
    #pragma unroll
    for (int i = 0; i < 4; i++)
        #pragma unroll
        for (int l = 0; l < 4; l++)
            outp[(ty * 4 + i) * 64 + tx * 4 + l] = acc[i][l];
}

// ---------------- reduce partials + normalize + softmax ---------------------
__global__ void kSoftmax(const float* __restrict__ t) {
    int bh = blockIdx.x;            // 0..7
    int h = bh & 1;
    __shared__ float s_attn[4096];
    __shared__ float s_rq[64], s_rk[64];
    if (threadIdx.x < 64) {
        s_rq[threadIdx.x] = 1.f / fmaxf(sqrtf(g_sqq[bh * 64 + threadIdx.x]), 1e-12f);
        s_rk[threadIdx.x] = 1.f / fmaxf(sqrtf(g_sqk[bh * 64 + threadIdx.x]), 1e-12f);
    }
    for (int idx = threadIdx.x; idx < 4096; idx += 256) {
        float s = 0.f;
        for (int ch = 0; ch < NCHUNK; ch++)
            s += g_attn_part[((size_t)ch * 8 + bh) * 4096 + idx];
        s_attn[idx] = s;
    }
    __syncthreads();
    if (threadIdx.x < 64) {
        int d = threadIdx.x;
        float tv = t[h];
        float row[64];
        float m = -1e30f;
        #pragma unroll
        for (int e2 = 0; e2 < 64; e2++) {
            float v = s_attn[d * 64 + e2] * s_rq[d] * s_rk[e2] * tv;
            row[e2] = v;
            m = fmaxf(m, v);
        }
        float ssum = 0.f;
        #pragma unroll
        for (int e2 = 0; e2 < 64; e2++) {
            row[e2] = expf(row[e2] - m);
            ssum += row[e2];
        }
        float inv = 1.f / ssum;
        #pragma unroll
        for (int e2 = 0; e2 < 64; e2++)
            g_attn[bh * 4096 + d * 64 + e2] = row[e2] * inv;
    }
}

// ---------------- GEMM2: out = attn @ v -------------------------------------
__global__ void __launch_bounds__(256, 2) kGemm2() {
    int nt = blockIdx.x;   // 144
    int bh = blockIdx.y;   // 8
    int n0 = nt * 256;
    __shared__ float4 s_a[1024];   // attn[d][e], e packed in float4
    float* s_af = (float*)s_a;
    for (int idx = threadIdx.x; idx < 4096; idx += 256)
        s_af[idx] = g_attn[bh * 4096 + idx];
    __syncthreads();

    float acc[64];
    #pragma unroll
    for (int d = 0; d < 64; d++) acc[d] = 0.f;

    const float* vp = g_v + (size_t)bh * Dn * HWn + n0 + threadIdx.x;
    for (int e4 = 0; e4 < 16; e4++) {
        float v0 = vp[(size_t)(e4 * 4 + 0) * HWn];
        float v1 = vp[(size_t)(e4 * 4 + 1) * HWn];
        float v2 = vp[(size_t)(e4 * 4 + 2) * HWn];
        float v3 = vp[(size_t)(e4 * 4 + 3) * HWn];
        #pragma unroll
        for (int d = 0; d < 64; d++) {
            float4 a = s_a[d * 16 + e4];
            acc[d] += a.x * v0 + a.y * v1 + a.z * v2 + a.w * v3;
        }
    }
    float* op = g_ao + (size_t)bh * Dn * HWn + n0 + threadIdx.x;
    #pragma unroll
    for (int d = 0; d < 64; d++) op[(size_t)d * HWn] = acc[d];
}

// ---------------- stage D: rearrange + depthwise fuse conv + leaky ----------
__global__ void kD(const float* __restrict__ w, const float* __restrict__ bias,
                   float* __restrict__ out) {
    int rt = blockIdx.x;  // 12
    int c  = blockIdx.y;  // 128
    int b  = blockIdx.z;  // 4
    int d = c >> 1, h = c & 1;
    const float* in = g_ao + ((size_t)(b * NHn + h) * Dn + d) * HWn;

    __shared__ float s_in[18][194];
    int r0 = rt * 16;
    for (int idx = threadIdx.x; idx < 18 * 194; idx += 256) {
        int rr = idx / 194, cc = idx % 194;
        int gr = r0 + rr - 1, gc = cc - 1;
        float v = 0.f;
        if (gr >= 0 && gr < Hn && gc >= 0 && gc < Wn) v = in[gr * Wn + gc];
        s_in[rr][cc] = v;
    }
    __syncthreads();

    const float* wp = w + c * 9;
    float w0 = wp[0], w1 = wp[1], w2 = wp[2], w3 = wp[3], w4 = wp[4],
          w5 = wp[5], w6 = wp[6], w7 = wp[7], w8 = wp[8];
    float bb = bias[c];
    float* outp = out + (size_t)(b * Cn + c) * HWn;
    for (int pix = threadIdx.x; pix < 16 * Wn; pix += 256) {
        int lr = pix / Wn, lc = pix % Wn;
        float acc = bb
            + w0 * s_in[lr][lc]     + w1 * s_in[lr][lc + 1]     + w2 * s_in[lr][lc + 2]
            + w3 * s_in[lr + 1][lc] + w4 * s_in[lr + 1][lc + 1] + w5 * s_in[lr + 1][lc + 2]
            + w6 * s_in[lr + 2][lc] + w7 * s_in[lr + 2][lc + 1] + w8 * s_in[lr + 2][lc + 2];
        acc = (acc >= 0.f) ? acc : 0.05f * acc;
        outp[(r0 + lr) * Wn + lc] = acc;
    }
}

// ---------------- launch ----------------------------------------------------
extern "C" void kernel_launch(void* const* d_in, const int* in_sizes, int n_in,
                              void* d_out, int out_size) {
    const float* x     = (const float*)d_in[0];
    const float* ir    = (const float*)d_in[1];
    const float* w_qkv = (const float*)d_in[2];
    const float* b_qkv = (const float*)d_in[3];
    const float* gamma = (const float*)d_in[4];
    const float* beta  = (const float*)d_in[5];
    const float* wq    = (const float*)d_in[6];
    const float* bq    = (const float*)d_in[7];
    const float* wk    = (const float*)d_in[8];
    const float* bk    = (const float*)d_in[9];
    const float* wv    = (const float*)d_in[10];
    const float* bv    = (const float*)d_in[11];
    const float* t     = (const float*)d_in[12];
    const float* w_fus = (const float*)d_in[13];
    const float* b_fus = (const float*)d_in[14];
    float* out = (float*)d_out;

    void *pSum, *pSq, *pQ, *pK, *pV, *pSqq, *pSqk;
    cudaGetSymbolAddress(&pSum, g_sum);
    cudaGetSymbolAddress(&pSq, g_sumsq);
    cudaGetSymbolAddress(&pQ, g_q);
    cudaGetSymbolAddress(&pK, g_k);
    cudaGetSymbolAddress(&pV, g_v);
    cudaGetSymbolAddress(&pSqq, g_sqq);
    cudaGetSymbolAddress(&pSqk, g_sqk);

    cudaMemsetAsync(pSum, 0, NPLANES * sizeof(float));
    cudaMemsetAsync(pSq, 0, NPLANES * sizeof(float));
    cudaMemsetAsync(pSqq, 0, Bn * NHn * Dn * sizeof(float));
    cudaMemsetAsync(pSqk, 0, Bn * NHn * Dn * sizeof(float));

    kA<<<dim3(12, 128, 8), 256>>>(x, ir, w_qkv, b_qkv);
    kFin<<<(NPLANES + 255) / 256, 256>>>(gamma, beta);

    kB<<<dim3(144, 8, 12), 256>>>(wq, bq, wk, bk, wv, bv,
                                  (float*)pQ, (float*)pK, (float*)pV);

    kGemm1<<<dim3(NCHUNK, 8), 256>>>();
    kSoftmax<<<8, 256>>>(t);
    kGemm2<<<dim3(144, 8), 256>>>();

    kD<<<dim3(12, 128, 4), 256>>>(w_fus, b_fus, out);
}